// round 1
// baseline (speedup 1.0000x reference)
#include <cuda_runtime.h>

#define BN 8
#define JN 64
#define CN 32
#define HT 8
#define HIMG_ 256
#define WIMG_ 256
#define HW (HIMG_*WIMG_)

// mask_mode: 0 = float mask after res, 1 = uint8 mask packed after res, 2 = no mask
__global__ void roirotate_kernel(const float* __restrict__ image,
                                 const float* __restrict__ boxes,
                                 float* __restrict__ out,
                                 int max_w, int mask_mode)
{
    int bj = blockIdx.x;               // 0 .. B*J-1
    int b  = bj / JN;

    const float* bx = boxes + bj * 5;
    float l   = bx[0];
    float t   = bx[1];
    float r   = bx[2];
    float btm = bx[3];

    float bw = __fsub_rn(r, l);
    float bh = __fsub_rn(btm, t);
    // widths = int32( (bw/bh) * 8 )  in float32 arithmetic, truncation toward zero
    int width = (int)(__fmul_rn(__fdiv_rn(bw, bh), 8.0f));
    float each_w = __fdiv_rn(bw, (float)(width - 1));
    float each_h = __fdiv_rn(bh, 7.0f);   // HEIGHT-1 = 7

    const float* imgb = image + (size_t)b * CN * HW;
    float* outb = out + (size_t)bj * CN * HT * max_w;

    // ---- mask ----
    if (mask_mode == 0) {
        float* maskp = out + (size_t)BN * JN * CN * HT * max_w + (size_t)bj * max_w;
        for (int k = threadIdx.x; k < max_w; k += blockDim.x)
            maskp[k] = (k < width) ? 1.0f : 0.0f;
    } else if (mask_mode == 1) {
        unsigned char* maskp =
            (unsigned char*)(out + (size_t)BN * JN * CN * HT * max_w) + (size_t)bj * max_w;
        for (int k = threadIdx.x; k < max_w; k += blockDim.x)
            maskp[k] = (k < width) ? (unsigned char)1 : (unsigned char)0;
    }

    // ---- res: each thread owns one (i, k), loops over 32 channels ----
    int total = HT * max_w;
    for (int idx = threadIdx.x; idx < total; idx += blockDim.x) {
        int k = idx % max_w;
        int i = idx / max_w;
        float* op = outb + (size_t)i * max_w + k;

        if (k >= width) {
            // masked region -> zeros (output buffer is poisoned, must write)
            #pragma unroll
            for (int c = 0; c < CN; c++)
                op[(size_t)c * HT * max_w] = 0.0f;
            continue;
        }

        // coordinate generation: match JAX float32 mul-then-add exactly (no FMA)
        float x = __fadd_rn(__fmul_rn((float)k, each_w), l);
        float y = __fadd_rn(__fmul_rn((float)i, each_h), t);

        float fx = floorf(x), fy = floorf(y);
        int x0 = min(max((int)fx,     0), WIMG_ - 1);
        int x1 = min(max((int)fx + 1, 0), WIMG_ - 1);
        int y0 = min(max((int)fy,     0), HIMG_ - 1);
        int y1 = min(max((int)fy + 1, 0), HIMG_ - 1);

        float x0f = (float)x0, x1f = (float)x1;
        float y0f = (float)y0, y1f = (float)y1;
        float wa = (x1f - x) * (y1f - y);   // (y0,x0)
        float wb = (x1f - x) * (y - y0f);   // (y1,x0)
        float wc = (x - x0f) * (y1f - y);   // (y0,x1)
        float wd = (x - x0f) * (y - y0f);   // (y1,x1)

        int o00 = y0 * WIMG_ + x0;
        int o10 = y1 * WIMG_ + x0;
        int o01 = y0 * WIMG_ + x1;
        int o11 = y1 * WIMG_ + x1;

        #pragma unroll 4
        for (int c = 0; c < CN; c++) {
            const float* ip = imgb + (size_t)c * HW;
            float v = __ldg(ip + o00) * wa
                    + __ldg(ip + o10) * wb
                    + __ldg(ip + o01) * wc
                    + __ldg(ip + o11) * wd;
            op[(size_t)c * HT * max_w] = v;
        }
    }
}

extern "C" void kernel_launch(void* const* d_in, const int* in_sizes, int n_in,
                              void* d_out, int out_size)
{
    const float* image = (const float*)d_in[0];
    const float* boxes = (const float*)d_in[1];
    float* out = (float*)d_out;

    // Derive max_w from out_size (host-side, no sync needed).
    // res elems per unit max_w: B*J*C*H = 131072 ; mask elems per unit: B*J = 512
    const long long per_res = (long long)BN * JN * CN * HT;     // 131072
    const long long per_fmask = per_res + (long long)BN * JN;   // 131584 (float mask)
    const long long per_u8 = per_res + (long long)BN * JN / 4;  // 131200 (u8 mask packed into f32 elems)

    int max_w, mask_mode;
    long long osz = (long long)out_size;
    if (osz % per_fmask == 0) {
        max_w = (int)(osz / per_fmask);
        mask_mode = 0;
    } else if (osz % per_u8 == 0) {
        max_w = (int)(osz / per_u8);
        mask_mode = 1;
    } else if (osz % per_res == 0) {
        max_w = (int)(osz / per_res);
        mask_mode = 2;
    } else {
        // fallback: assume float-mask layout, round down
        max_w = (int)(osz / per_fmask);
        mask_mode = 0;
    }

    dim3 grid(BN * JN);
    dim3 block(256);
    roirotate_kernel<<<grid, block>>>(image, boxes, out, max_w, mask_mode);
}

// round 2
// speedup vs baseline: 1.5057x; 1.5057x over previous
#include <cuda_runtime.h>

#define BN 8
#define JN 64
#define CN 32
#define HT 8
#define HIMG_ 256
#define WIMG_ 256
#define HW (HIMG_*WIMG_)

// mask_mode: 0 = float mask after res, 1 = uint8 mask packed after res, 2 = no mask
__global__ void roirotate_kernel(const float* __restrict__ image,
                                 const float* __restrict__ boxes,
                                 float* __restrict__ out,
                                 int max_w, int mask_mode)
{
    int bj = blockIdx.y;               // 0 .. B*J-1
    int b  = bj / JN;

    const float* bx = boxes + bj * 5;
    float l   = bx[0];
    float t   = bx[1];
    float r   = bx[2];
    float btm = bx[3];

    float bw = __fsub_rn(r, l);
    float bh = __fsub_rn(btm, t);
    // widths = int32( (bw/bh) * 8 )  in float32 arithmetic, truncation toward zero
    int width = (int)(__fmul_rn(__fdiv_rn(bw, bh), 8.0f));
    float each_w = __fdiv_rn(bw, (float)(width - 1));
    float each_h = __fdiv_rn(bh, 7.0f);   // HEIGHT-1 = 7

    const float* imgb = image + (size_t)b * CN * HW;
    float* outb = out + (size_t)bj * CN * HT * max_w;

    int idx = blockIdx.x * blockDim.x + threadIdx.x;   // over HT*max_w

    // ---- mask (only the first slice of blocks writes it) ----
    if (blockIdx.x == 0) {
        if (mask_mode == 0) {
            float* maskp = out + (size_t)BN * JN * CN * HT * max_w + (size_t)bj * max_w;
            for (int k = threadIdx.x; k < max_w; k += blockDim.x)
                maskp[k] = (k < width) ? 1.0f : 0.0f;
        } else if (mask_mode == 1) {
            unsigned char* maskp =
                (unsigned char*)(out + (size_t)BN * JN * CN * HT * max_w) + (size_t)bj * max_w;
            for (int k = threadIdx.x; k < max_w; k += blockDim.x)
                maskp[k] = (k < width) ? (unsigned char)1 : (unsigned char)0;
        }
    }

    if (idx >= HT * max_w) return;

    int k = idx % max_w;
    int i = idx / max_w;
    float* op = outb + (size_t)i * max_w + k;
    const size_t cstride = (size_t)HT * max_w;

    if (k >= width) {
        // masked region -> zeros (output buffer is poisoned, must write)
        #pragma unroll
        for (int c = 0; c < CN; c++)
            op[c * cstride] = 0.0f;
        return;
    }

    // coordinate generation: match JAX float32 mul-then-add exactly (no FMA)
    float x = __fadd_rn(__fmul_rn((float)k, each_w), l);
    float y = __fadd_rn(__fmul_rn((float)i, each_h), t);

    float fx = floorf(x), fy = floorf(y);
    int x0 = min(max((int)fx,     0), WIMG_ - 1);
    int x1 = min(max((int)fx + 1, 0), WIMG_ - 1);
    int y0 = min(max((int)fy,     0), HIMG_ - 1);
    int y1 = min(max((int)fy + 1, 0), HIMG_ - 1);

    float x0f = (float)x0, x1f = (float)x1;
    float y0f = (float)y0, y1f = (float)y1;
    float wa = (x1f - x) * (y1f - y);   // (y0,x0)
    float wb = (x1f - x) * (y - y0f);   // (y1,x0)
    float wc = (x - x0f) * (y1f - y);   // (y0,x1)
    float wd = (x - x0f) * (y - y0f);   // (y1,x1)

    int o00 = y0 * WIMG_ + x0;
    int o10 = y1 * WIMG_ + x0;
    int o01 = y0 * WIMG_ + x1;
    int o11 = y1 * WIMG_ + x1;

    #pragma unroll 8
    for (int c = 0; c < CN; c++) {
        const float* ip = imgb + (size_t)c * HW;
        float v = __ldg(ip + o00) * wa
                + __ldg(ip + o10) * wb
                + __ldg(ip + o01) * wc
                + __ldg(ip + o11) * wd;
        op[c * cstride] = v;
    }
}

extern "C" void kernel_launch(void* const* d_in, const int* in_sizes, int n_in,
                              void* d_out, int out_size)
{
    const float* image = (const float*)d_in[0];
    const float* boxes = (const float*)d_in[1];
    float* out = (float*)d_out;

    // Derive max_w from out_size (host-side, no sync needed).
    // res elems per unit max_w: B*J*C*H = 131072 ; mask elems per unit: B*J = 512
    const long long per_res = (long long)BN * JN * CN * HT;     // 131072
    const long long per_fmask = per_res + (long long)BN * JN;   // 131584 (float mask)
    const long long per_u8 = per_res + (long long)BN * JN / 4;  // 131200 (u8 mask packed into f32 elems)

    int max_w, mask_mode;
    long long osz = (long long)out_size;
    if (osz % per_fmask == 0) {
        max_w = (int)(osz / per_fmask);
        mask_mode = 0;
    } else if (osz % per_u8 == 0) {
        max_w = (int)(osz / per_u8);
        mask_mode = 1;
    } else if (osz % per_res == 0) {
        max_w = (int)(osz / per_res);
        mask_mode = 2;
    } else {
        // fallback: assume float-mask layout, round down
        max_w = (int)(osz / per_fmask);
        mask_mode = 0;
    }

    const int block = 256;
    int slices = (HT * max_w + block - 1) / block;
    dim3 grid(slices, BN * JN);
    roirotate_kernel<<<grid, block>>>(image, boxes, out, max_w, mask_mode);
}

// round 3
// speedup vs baseline: 1.7854x; 1.1858x over previous
#include <cuda_runtime.h>

#define BN 8
#define JN 64
#define CN 32
#define CG 8               // channels per block (grid.z = CN/CG = 4)
#define HT 8
#define HIMG_ 256
#define WIMG_ 256
#define HW (HIMG_*WIMG_)

// mask_mode: 0 = float mask after res, 1 = uint8 mask packed after res, 2 = no mask
__global__ void __launch_bounds__(256)
roirotate_kernel(const float* __restrict__ image,
                 const float* __restrict__ boxes,
                 float* __restrict__ out,
                 int max_w, int mask_mode)
{
    int bj = blockIdx.y;               // 0 .. B*J-1
    int b  = bj / JN;
    int c0 = blockIdx.z * CG;          // first channel of this block's group

    const float* bx = boxes + bj * 5;
    float l   = bx[0];
    float t   = bx[1];
    float r   = bx[2];
    float btm = bx[3];

    float bw = __fsub_rn(r, l);
    float bh = __fsub_rn(btm, t);
    // widths = int32( (bw/bh) * 8 )  in float32 arithmetic, truncation toward zero
    int width = (int)(__fmul_rn(__fdiv_rn(bw, bh), 8.0f));
    float each_w = __fdiv_rn(bw, (float)(width - 1));
    float each_h = __fdiv_rn(bh, 7.0f);   // HEIGHT-1 = 7

    const float* imgb = image + (size_t)b * CN * HW + (size_t)c0 * HW;
    float* outb = out + (size_t)bj * CN * HT * max_w + (size_t)c0 * HT * max_w;

    int idx = blockIdx.x * blockDim.x + threadIdx.x;   // over HT*max_w

    // ---- mask (only one slice of blocks writes it) ----
    if (blockIdx.x == 0 && blockIdx.z == 0) {
        if (mask_mode == 0) {
            float* maskp = out + (size_t)BN * JN * CN * HT * max_w + (size_t)bj * max_w;
            for (int k = threadIdx.x; k < max_w; k += blockDim.x)
                maskp[k] = (k < width) ? 1.0f : 0.0f;
        } else if (mask_mode == 1) {
            unsigned char* maskp =
                (unsigned char*)(out + (size_t)BN * JN * CN * HT * max_w) + (size_t)bj * max_w;
            for (int k = threadIdx.x; k < max_w; k += blockDim.x)
                maskp[k] = (k < width) ? (unsigned char)1 : (unsigned char)0;
        }
    }

    if (idx >= HT * max_w) return;

    int k = idx % max_w;
    int i = idx / max_w;
    float* op = outb + (size_t)i * max_w + k;
    const size_t cstride = (size_t)HT * max_w;

    if (k >= width) {
        // masked region -> zeros (output buffer is poisoned, must write)
        #pragma unroll
        for (int c = 0; c < CG; c++)
            op[c * cstride] = 0.0f;
        return;
    }

    // coordinate generation: match JAX float32 mul-then-add exactly (no FMA)
    float x = __fadd_rn(__fmul_rn((float)k, each_w), l);
    float y = __fadd_rn(__fmul_rn((float)i, each_h), t);

    float fx = floorf(x), fy = floorf(y);
    int x0 = min(max((int)fx,     0), WIMG_ - 1);
    int x1 = min(max((int)fx + 1, 0), WIMG_ - 1);
    int y0 = min(max((int)fy,     0), HIMG_ - 1);
    int y1 = min(max((int)fy + 1, 0), HIMG_ - 1);

    float x0f = (float)x0, x1f = (float)x1;
    float y0f = (float)y0, y1f = (float)y1;
    float wa = (x1f - x) * (y1f - y);   // (y0,x0)
    float wb = (x1f - x) * (y - y0f);   // (y1,x0)
    float wc = (x - x0f) * (y1f - y);   // (y0,x1)
    float wd = (x - x0f) * (y - y0f);   // (y1,x1)

    int o00 = y0 * WIMG_ + x0;
    int o10 = y1 * WIMG_ + x0;
    int o01 = y0 * WIMG_ + x1;
    int o11 = y1 * WIMG_ + x1;

    // Batch ALL loads for the 8-channel group first -> 32 independent LDGs
    // in flight per thread, then do the math + coalesced stores.
    float v00[CG], v10[CG], v01[CG], v11[CG];
    #pragma unroll
    for (int c = 0; c < CG; c++) {
        const float* ip = imgb + (size_t)c * HW;
        v00[c] = __ldg(ip + o00);
        v10[c] = __ldg(ip + o10);
        v01[c] = __ldg(ip + o01);
        v11[c] = __ldg(ip + o11);
    }
    #pragma unroll
    for (int c = 0; c < CG; c++) {
        op[c * cstride] = v00[c] * wa + v10[c] * wb + v01[c] * wc + v11[c] * wd;
    }
}

extern "C" void kernel_launch(void* const* d_in, const int* in_sizes, int n_in,
                              void* d_out, int out_size)
{
    const float* image = (const float*)d_in[0];
    const float* boxes = (const float*)d_in[1];
    float* out = (float*)d_out;

    // Derive max_w from out_size (host-side, no sync needed).
    // res elems per unit max_w: B*J*C*H = 131072 ; mask elems per unit: B*J = 512
    const long long per_res = (long long)BN * JN * CN * HT;     // 131072
    const long long per_fmask = per_res + (long long)BN * JN;   // 131584 (float mask)
    const long long per_u8 = per_res + (long long)BN * JN / 4;  // 131200 (u8 mask packed into f32 elems)

    int max_w, mask_mode;
    long long osz = (long long)out_size;
    if (osz % per_fmask == 0) {
        max_w = (int)(osz / per_fmask);
        mask_mode = 0;
    } else if (osz % per_u8 == 0) {
        max_w = (int)(osz / per_u8);
        mask_mode = 1;
    } else if (osz % per_res == 0) {
        max_w = (int)(osz / per_res);
        mask_mode = 2;
    } else {
        // fallback: assume float-mask layout, round down
        max_w = (int)(osz / per_fmask);
        mask_mode = 0;
    }

    const int block = 256;
    int slices = (HT * max_w + block - 1) / block;
    dim3 grid(slices, BN * JN, CN / CG);
    roirotate_kernel<<<grid, block>>>(image, boxes, out, max_w, mask_mode);
}